// round 3
// baseline (speedup 1.0000x reference)
#include <cuda_runtime.h>
#include <math.h>

// Causal multi-head attention, fp32, flash-attention style.
// B=4 (runtime), N=2048 (runtime), H=16, Hd=64. Layout [B, N, H*Hd].

#define NUM_HEADS 16
#define HEAD_DIM  64
#define DMODEL    (NUM_HEADS * HEAD_DIM)   // 1024
#define BM        64
#define BN        64
#define PAD       68                       // 64 + 4 : conflict-free LDS.128 phases
#define NTHREADS  256

__global__ __launch_bounds__(NTHREADS, 2)
void attn_causal_kernel(const float* __restrict__ Q,
                        const float* __restrict__ K,
                        const float* __restrict__ V,
                        float* __restrict__ O,
                        int N)
{
    extern __shared__ float smem[];
    float* sQ  = smem;                 // [64][PAD]  Q tile (pre-scaled)
    float* sK  = smem + 1 * BM * PAD;  // [64][PAD]  K tile, [n][d]
    float* sVt = smem + 2 * BM * PAD;  // [64][PAD]  V tile transposed, [d][n]
    float* sP  = smem + 3 * BM * PAD;  // [64][PAD]  softmax probs tile

    const int tid = threadIdx.x;
    const int ty  = tid >> 4;   // 0..15  (row group; 16 threads share a row)
    const int tx  = tid & 15;   // 0..15  (col group)

    // Reverse block order: longest (largest qtile) CTAs start first.
    const int qtile = (int)gridDim.x - 1 - (int)blockIdx.x;
    const int h     = blockIdx.y;
    const int b     = blockIdx.z;
    const int qbase = qtile * BM;

    // base offset of (b, row=0, head h, d=0) — shared by Q,K,V,O
    const size_t base = (size_t)b * N * DMODEL + (size_t)h * HEAD_DIM;

    // ---- load Q tile (pre-scaled by 1/sqrt(Hd)) ----
    const float scale = 0.125f;
    {
        int idx = tid;                     // 64 rows * 16 float4 = 1024 float4
        #pragma unroll
        for (int t = 0; t < 4; ++t) {
            const int r  = idx >> 4;
            const int c4 = idx & 15;
            const float4 val = *(const float4*)(Q + base + (size_t)(qbase + r) * DMODEL + c4 * 4);
            float* dst = sQ + r * PAD + c4 * 4;
            dst[0] = val.x * scale; dst[1] = val.y * scale;
            dst[2] = val.z * scale; dst[3] = val.w * scale;
            idx += NTHREADS;
        }
    }

    float acc[4][4];
    float m_i[4], l_i[4];
    #pragma unroll
    for (int i = 0; i < 4; ++i) {
        m_i[i] = -1e30f;
        l_i[i] = 0.0f;
        #pragma unroll
        for (int j = 0; j < 4; ++j) acc[i][j] = 0.0f;
    }

    for (int kt = 0; kt <= qtile; ++kt) {
        const int kbase = kt * BM;
        __syncthreads();   // prev iteration done reading sK / sVt / sP

        // ---- load K tile [n][d] and V tile transposed [d][n] ----
        {
            int idx = tid;
            #pragma unroll
            for (int t = 0; t < 4; ++t) {
                const int r  = idx >> 4;
                const int c4 = idx & 15;
                const float4 val = *(const float4*)(K + base + (size_t)(kbase + r) * DMODEL + c4 * 4);
                float* dst = sK + r * PAD + c4 * 4;
                dst[0] = val.x; dst[1] = val.y; dst[2] = val.z; dst[3] = val.w;
                idx += NTHREADS;
            }
            idx = tid;
            #pragma unroll
            for (int t = 0; t < 4; ++t) {
                const int r  = idx >> 4;
                const int c4 = idx & 15;
                const float4 val = *(const float4*)(V + base + (size_t)(kbase + r) * DMODEL + c4 * 4);
                sVt[(c4 * 4 + 0) * PAD + r] = val.x;
                sVt[(c4 * 4 + 1) * PAD + r] = val.y;
                sVt[(c4 * 4 + 2) * PAD + r] = val.z;
                sVt[(c4 * 4 + 3) * PAD + r] = val.w;
                idx += NTHREADS;
            }
        }
        __syncthreads();

        // ---- S = Qs @ K^T  (4x4 microtile, rows ty+16i, cols tx+16j) ----
        float s[4][4];
        #pragma unroll
        for (int i = 0; i < 4; ++i)
            #pragma unroll
            for (int j = 0; j < 4; ++j) s[i][j] = 0.0f;

        #pragma unroll 4
        for (int k4 = 0; k4 < 16; ++k4) {
            float4 av[4], bv[4];
            #pragma unroll
            for (int i = 0; i < 4; ++i)
                av[i] = *(const float4*)(sQ + (ty + 16 * i) * PAD + k4 * 4);
            #pragma unroll
            for (int j = 0; j < 4; ++j)
                bv[j] = *(const float4*)(sK + (tx + 16 * j) * PAD + k4 * 4);
            #pragma unroll
            for (int i = 0; i < 4; ++i)
                #pragma unroll
                for (int j = 0; j < 4; ++j) {
                    s[i][j] = fmaf(av[i].x, bv[j].x, s[i][j]);
                    s[i][j] = fmaf(av[i].y, bv[j].y, s[i][j]);
                    s[i][j] = fmaf(av[i].z, bv[j].z, s[i][j]);
                    s[i][j] = fmaf(av[i].w, bv[j].w, s[i][j]);
                }
        }

        // ---- causal mask (diagonal tile only; qbase == kbase there) ----
        if (kt == qtile) {
            #pragma unroll
            for (int i = 0; i < 4; ++i)
                #pragma unroll
                for (int j = 0; j < 4; ++j)
                    if (tx + 16 * j > ty + 16 * i) s[i][j] = -1e30f;
        }

        // ---- online softmax update ----
        #pragma unroll
        for (int i = 0; i < 4; ++i) {
            float rm = fmaxf(fmaxf(s[i][0], s[i][1]), fmaxf(s[i][2], s[i][3]));
            #pragma unroll
            for (int off = 1; off < 16; off <<= 1)
                rm = fmaxf(rm, __shfl_xor_sync(0xffffffffu, rm, off));
            const float mn    = fmaxf(m_i[i], rm);
            const float alpha = __expf(m_i[i] - mn);
            m_i[i] = mn;

            float rs = 0.0f;
            #pragma unroll
            for (int j = 0; j < 4; ++j) {
                s[i][j] = __expf(s[i][j] - mn);
                rs += s[i][j];
            }
            #pragma unroll
            for (int off = 1; off < 16; off <<= 1)
                rs += __shfl_xor_sync(0xffffffffu, rs, off);
            l_i[i] = l_i[i] * alpha + rs;

            #pragma unroll
            for (int j = 0; j < 4; ++j) {
                acc[i][j] *= alpha;
                sP[(ty + 16 * i) * PAD + tx + 16 * j] = s[i][j];
            }
        }
        __syncthreads();

        // ---- O += P @ V  (vectorized over n via sP rows / sVt rows) ----
        #pragma unroll 4
        for (int n4 = 0; n4 < 16; ++n4) {
            float4 av[4], bv[4];
            #pragma unroll
            for (int i = 0; i < 4; ++i)
                av[i] = *(const float4*)(sP + (ty + 16 * i) * PAD + n4 * 4);
            #pragma unroll
            for (int j = 0; j < 4; ++j)
                bv[j] = *(const float4*)(sVt + (tx + 16 * j) * PAD + n4 * 4);
            #pragma unroll
            for (int i = 0; i < 4; ++i)
                #pragma unroll
                for (int j = 0; j < 4; ++j) {
                    acc[i][j] = fmaf(av[i].x, bv[j].x, acc[i][j]);
                    acc[i][j] = fmaf(av[i].y, bv[j].y, acc[i][j]);
                    acc[i][j] = fmaf(av[i].z, bv[j].z, acc[i][j]);
                    acc[i][j] = fmaf(av[i].w, bv[j].w, acc[i][j]);
                }
        }
    }

    // ---- epilogue: normalize and write ----
    #pragma unroll
    for (int i = 0; i < 4; ++i) {
        const float inv = 1.0f / l_i[i];
        float* row = O + base + (size_t)(qbase + ty + 16 * i) * DMODEL;
        #pragma unroll
        for (int j = 0; j < 4; ++j)
            row[tx + 16 * j] = acc[i][j] * inv;
    }
}

extern "C" void kernel_launch(void* const* d_in, const int* in_sizes, int n_in,
                              void* d_out, int out_size)
{
    const float* q = (const float*)d_in[0];
    const float* k = (const float*)d_in[1];
    const float* v = (const float*)d_in[2];
    // d_in[3] is the causal mask (tril) — causality is applied analytically.
    float* out = (float*)d_out;

    // Derive N from mask size (N*N), B from q size.
    int N = 2048;
    if (n_in >= 4 && in_sizes[3] > 0) {
        double nn = sqrt((double)in_sizes[3]);
        N = (int)(nn + 0.5);
    }
    int B = in_sizes[0] / (N * DMODEL);

    static int smem_set = -1;
    const int smem_bytes = 4 * BM * PAD * (int)sizeof(float);  // 69632
    if (smem_set != smem_bytes) {
        cudaFuncSetAttribute(attn_causal_kernel,
                             cudaFuncAttributeMaxDynamicSharedMemorySize, smem_bytes);
        smem_set = smem_bytes;
    }

    dim3 grid(N / BM, NUM_HEADS, B);
    dim3 block(NTHREADS, 1, 1);
    attn_causal_kernel<<<grid, block, smem_bytes>>>(q, k, v, out, N);
}

// round 4
// speedup vs baseline: 1.2769x; 1.2769x over previous
#include <cuda_runtime.h>
#include <math.h>

// Causal MHA, fp32, flash-attention style with packed f32x2 (FFMA2) math.
// B=4, N=2048 (runtime), H=16, Hd=64. Layout [B, N, H*Hd].
// Tile: BM=128 q-rows x BN=128 k-cols, 256 threads, 8x8 outputs/thread,
// i-packed f32x2 accumulators (each u64 acc = two adjacent Q rows).

#define NUM_HEADS 16
#define HEAD_DIM  64
#define DMODEL    (NUM_HEADS * HEAD_DIM)   // 1024
#define BM        128
#define BN        128
#define NT        256

#define SQT_S 132   // sQt row stride (128 i + 4): stride%32==4 -> conflict-free
#define SK_S  68    // sK/sV row stride (64 + 4)
#define SPT_S 132   // sPt row stride (128 i + 4)

typedef unsigned long long u64;

__device__ __forceinline__ u64 dup2f(float x) {
    u64 r; asm("mov.b64 %0, {%1, %1};" : "=l"(r) : "f"(x)); return r;
}
__device__ __forceinline__ u64 pack2f(float x, float y) {
    u64 r; asm("mov.b64 %0, {%1, %2};" : "=l"(r) : "f"(x), "f"(y)); return r;
}
__device__ __forceinline__ void unpack2f(u64 v, float &x, float &y) {
    asm("mov.b64 {%0, %1}, %2;" : "=f"(x), "=f"(y) : "l"(v));
}
__device__ __forceinline__ void fma2(u64 &d, u64 a, u64 b) {
    asm("fma.rn.f32x2 %0, %1, %2, %0;" : "+l"(d) : "l"(a), "l"(b));
}
__device__ __forceinline__ void mul2(u64 &d, u64 a) {
    asm("mul.rn.f32x2 %0, %0, %1;" : "+l"(d) : "l"(a));
}
__device__ __forceinline__ float ex2(float x) {
    float r; asm("ex2.approx.f32 %0, %1;" : "=f"(r) : "f"(x)); return r;
}

__global__ __launch_bounds__(NT)
void attn_causal_kernel(const float* __restrict__ Q,
                        const float* __restrict__ K,
                        const float* __restrict__ V,
                        float* __restrict__ O,
                        int N)
{
    extern __shared__ float smem[];
    float* sQt = smem;                        // [64][SQT_S]  Q^T, pre-scaled
    float* sK  = sQt + 64 * SQT_S;            // [128][SK_S]  K natural [j][k]
    float* sV  = sK  + 128 * SK_S;            // [128][SK_S]  V natural [n][d]
    float* sPt = sV  + 128 * SK_S;            // [128][SPT_S] P^T  [n][i]

    const int tid = threadIdx.x;
    const int ty  = tid >> 4;    // 0..15 : owns i = ty*8 .. ty*8+7
    const int tx  = tid & 15;    // 0..15 : owns j = tx+16*jj, d = tx*4..tx*4+3

    const int qtile = (int)gridDim.x - 1 - (int)blockIdx.x;  // long CTAs first
    const int h     = blockIdx.y;
    const int b     = blockIdx.z;
    const int qbase = qtile * BM;
    const size_t base = (size_t)b * N * DMODEL + (size_t)h * HEAD_DIM;

    // ---- Q load + transpose + scale (1/8 * log2(e); exp done in log2 domain) ----
    const float scale = 0.18033688011112042f;
    {
        #pragma unroll
        for (int t = 0; t < 8; ++t) {
            const int idx = tid + t * NT;
            const int r = idx >> 4, c4 = idx & 15;
            const float4 v = *(const float4*)(Q + base + (size_t)(qbase + r) * DMODEL + c4 * 4);
            sQt[(c4 * 4 + 0) * SQT_S + r] = v.x * scale;
            sQt[(c4 * 4 + 1) * SQT_S + r] = v.y * scale;
            sQt[(c4 * 4 + 2) * SQT_S + r] = v.z * scale;
            sQt[(c4 * 4 + 3) * SQT_S + r] = v.w * scale;
        }
    }

    u64 oAcc[4][4];          // [ip][dd] : packed (O[2ip], O[2ip+1]) at d = tx*4+dd
    float m_i[8], l_i[8];
    #pragma unroll
    for (int i = 0; i < 4; ++i) {
        #pragma unroll
        for (int j = 0; j < 4; ++j) oAcc[i][j] = 0ull;
    }
    #pragma unroll
    for (int r = 0; r < 8; ++r) { m_i[r] = -1e30f; l_i[r] = 0.0f; }

    for (int kt = 0; kt <= qtile; ++kt) {
        __syncthreads();   // prev iter done reading sK/sV/sPt

        // ---- load K,V tiles (natural layouts, conflict-free) ----
        const size_t kb = base + (size_t)(kt * BN) * DMODEL;
        #pragma unroll
        for (int t = 0; t < 8; ++t) {
            const int idx = tid + t * NT;
            const int r = idx >> 4, c4 = idx & 15;
            const float4 kv = *(const float4*)(K + kb + (size_t)r * DMODEL + c4 * 4);
            *(float4*)(sK + r * SK_S + c4 * 4) = kv;
            const float4 vv = *(const float4*)(V + kb + (size_t)r * DMODEL + c4 * 4);
            *(float4*)(sV + r * SK_S + c4 * 4) = vv;
        }
        __syncthreads();

        // ---- GEMM1: S = Qs @ K^T, i-packed f32x2, 8x8 microtile ----
        u64 sAcc[4][8];      // [ip][jj]: packed (S[2ip][j], S[2ip+1][j]), j = tx+16jj
        #pragma unroll
        for (int i = 0; i < 4; ++i) {
            #pragma unroll
            for (int j = 0; j < 8; ++j) sAcc[i][j] = 0ull;
        }

        #pragma unroll 2
        for (int k4 = 0; k4 < 16; ++k4) {
            float4 bq[8];
            #pragma unroll
            for (int jj = 0; jj < 8; ++jj)
                bq[jj] = *(const float4*)(sK + (tx + 16 * jj) * SK_S + k4 * 4);
            #pragma unroll
            for (int q = 0; q < 4; ++q) {
                const float* aRow = sQt + (k4 * 4 + q) * SQT_S + ty * 8;
                const ulonglong2 a01 = *(const ulonglong2*)(aRow);      // i pairs (0,1),(2,3)
                const ulonglong2 a23 = *(const ulonglong2*)(aRow + 4);  // i pairs (4,5),(6,7)
                #pragma unroll
                for (int jj = 0; jj < 8; ++jj) {
                    const float bs = (q == 0) ? bq[jj].x : (q == 1) ? bq[jj].y
                                   : (q == 2) ? bq[jj].z : bq[jj].w;
                    const u64 bb = dup2f(bs);
                    fma2(sAcc[0][jj], a01.x, bb);
                    fma2(sAcc[1][jj], a01.y, bb);
                    fma2(sAcc[2][jj], a23.x, bb);
                    fma2(sAcc[3][jj], a23.y, bb);
                }
            }
        }

        // ---- softmax (log2 domain) + rescale O + write P^T ----
        const bool diag = (kt == qtile);
        #pragma unroll
        for (int ip = 0; ip < 4; ++ip) {
            float se[8], so[8];
            #pragma unroll
            for (int jj = 0; jj < 8; ++jj) unpack2f(sAcc[ip][jj], se[jj], so[jj]);

            const int re = ty * 8 + 2 * ip;
            const int ro = re + 1;
            if (diag) {
                #pragma unroll
                for (int jj = 0; jj < 8; ++jj) {
                    const int j = tx + 16 * jj;
                    if (j > re) se[jj] = -1e30f;
                    if (j > ro) so[jj] = -1e30f;
                }
            }

            float me = se[0], mo = so[0];
            #pragma unroll
            for (int jj = 1; jj < 8; ++jj) { me = fmaxf(me, se[jj]); mo = fmaxf(mo, so[jj]); }
            #pragma unroll
            for (int off = 1; off < 16; off <<= 1) {
                me = fmaxf(me, __shfl_xor_sync(0xffffffffu, me, off));
                mo = fmaxf(mo, __shfl_xor_sync(0xffffffffu, mo, off));
            }

            const float mne = fmaxf(m_i[2 * ip],     me);
            const float mno = fmaxf(m_i[2 * ip + 1], mo);
            const float ae  = ex2(m_i[2 * ip]     - mne);
            const float ao  = ex2(m_i[2 * ip + 1] - mno);
            m_i[2 * ip]     = mne;
            m_i[2 * ip + 1] = mno;

            float rse = 0.0f, rso = 0.0f;
            #pragma unroll
            for (int jj = 0; jj < 8; ++jj) {
                se[jj] = ex2(se[jj] - mne);  rse += se[jj];
                so[jj] = ex2(so[jj] - mno);  rso += so[jj];
            }
            #pragma unroll
            for (int off = 1; off < 16; off <<= 1) {
                rse += __shfl_xor_sync(0xffffffffu, rse, off);
                rso += __shfl_xor_sync(0xffffffffu, rso, off);
            }
            l_i[2 * ip]     = l_i[2 * ip]     * ae + rse;
            l_i[2 * ip + 1] = l_i[2 * ip + 1] * ao + rso;

            const u64 ap = pack2f(ae, ao);
            #pragma unroll
            for (int dd = 0; dd < 4; ++dd) mul2(oAcc[ip][dd], ap);

            #pragma unroll
            for (int jj = 0; jj < 8; ++jj) {
                *(float2*)(sPt + (tx + 16 * jj) * SPT_S + ty * 8 + 2 * ip) =
                    make_float2(se[jj], so[jj]);
            }
        }
        __syncthreads();

        // ---- GEMM2: O += P @ V, i-packed, a = P^T vector pairs, b = V dup ----
        #pragma unroll 4
        for (int n = 0; n < BN; ++n) {
            const float* pRow = sPt + n * SPT_S + ty * 8;
            const ulonglong2 a01 = *(const ulonglong2*)(pRow);
            const ulonglong2 a23 = *(const ulonglong2*)(pRow + 4);
            const float4 vv = *(const float4*)(sV + n * SK_S + tx * 4);
            const u64 b0 = dup2f(vv.x), b1 = dup2f(vv.y);
            const u64 b2 = dup2f(vv.z), b3 = dup2f(vv.w);
            fma2(oAcc[0][0], a01.x, b0); fma2(oAcc[0][1], a01.x, b1);
            fma2(oAcc[0][2], a01.x, b2); fma2(oAcc[0][3], a01.x, b3);
            fma2(oAcc[1][0], a01.y, b0); fma2(oAcc[1][1], a01.y, b1);
            fma2(oAcc[1][2], a01.y, b2); fma2(oAcc[1][3], a01.y, b3);
            fma2(oAcc[2][0], a23.x, b0); fma2(oAcc[2][1], a23.x, b1);
            fma2(oAcc[2][2], a23.x, b2); fma2(oAcc[2][3], a23.x, b3);
            fma2(oAcc[3][0], a23.y, b0); fma2(oAcc[3][1], a23.y, b1);
            fma2(oAcc[3][2], a23.y, b2); fma2(oAcc[3][3], a23.y, b3);
        }
    }

    // ---- epilogue: normalize and write (coalesced float4 per row) ----
    #pragma unroll
    for (int ip = 0; ip < 4; ++ip) {
        const float ile = 1.0f / l_i[2 * ip];
        const float ilo = 1.0f / l_i[2 * ip + 1];
        float oe[4], oo[4];
        #pragma unroll
        for (int dd = 0; dd < 4; ++dd) unpack2f(oAcc[ip][dd], oe[dd], oo[dd]);

        const int rowe = qbase + ty * 8 + 2 * ip;
        float4 fe = make_float4(oe[0] * ile, oe[1] * ile, oe[2] * ile, oe[3] * ile);
        *(float4*)(O + base + (size_t)rowe * DMODEL + tx * 4) = fe;
        float4 fo = make_float4(oo[0] * ilo, oo[1] * ilo, oo[2] * ilo, oo[3] * ilo);
        *(float4*)(O + base + (size_t)(rowe + 1) * DMODEL + tx * 4) = fo;
    }
}

extern "C" void kernel_launch(void* const* d_in, const int* in_sizes, int n_in,
                              void* d_out, int out_size)
{
    const float* q = (const float*)d_in[0];
    const float* k = (const float*)d_in[1];
    const float* v = (const float*)d_in[2];
    // d_in[3] is the causal mask (tril) — causality applied analytically.
    float* out = (float*)d_out;

    int N = 2048;
    if (n_in >= 4 && in_sizes[3] > 0) {
        double nn = sqrt((double)in_sizes[3]);
        N = (int)(nn + 0.5);
    }
    int B = in_sizes[0] / (N * DMODEL);

    static int smem_set = -1;
    const int smem_bytes = (64 * SQT_S + 2 * 128 * SK_S + 128 * SPT_S) * (int)sizeof(float); // 171008
    if (smem_set != smem_bytes) {
        cudaFuncSetAttribute(attn_causal_kernel,
                             cudaFuncAttributeMaxDynamicSharedMemorySize, smem_bytes);
        smem_set = smem_bytes;
    }

    dim3 grid(N / BM, NUM_HEADS, B);
    dim3 block(NT, 1, 1);
    attn_causal_kernel<<<grid, block, smem_bytes>>>(q, k, v, out, N);
}

// round 7
// speedup vs baseline: 3.7890x; 2.9673x over previous
#include <cuda_runtime.h>
#include <math.h>
#include <stdint.h>

// Causal MHA, fp32 in/out, flash attention on mma.sync tf32 tensor cores.
// B=4, N=2048 (runtime), H=16, Hd=64. Layout [B, N, H*Hd].
// CTA: 128 q-rows x 1 head, 256 threads (8 warps); warp owns 16 rows x 128 cols.

#define NUM_HEADS 16
#define HEAD_DIM  64
#define DMODEL    (NUM_HEADS * HEAD_DIM)
#define BM        128
#define BN        128
#define NT        256

#define KS 72     // sK row stride (floats): conflict-free ld.shared.v2 B-frags
#define VS 68     // sV row stride (floats): conflict-free scalar B-frags

// smem float offsets: K double buf, V double buf
#define SK0 0
#define SK1 (128 * KS)
#define SV0 (2 * 128 * KS)
#define SV1 (2 * 128 * KS + 128 * VS)
#define SMEM_FLOATS (2 * 128 * KS + 2 * 128 * VS)
#define SMEM_BYTES  (SMEM_FLOATS * 4)          // 143360

#define SC 0.18033688011112042f   // (1/sqrt(64)) * log2(e), folded into Q

__device__ __forceinline__ uint32_t tf32_rna(float x) {
    uint32_t r; asm("cvt.rna.tf32.f32 %0, %1;" : "=r"(r) : "f"(x)); return r;
}
__device__ __forceinline__ float ex2f(float x) {
    float r; asm("ex2.approx.f32 %0, %1;" : "=f"(r) : "f"(x)); return r;
}
__device__ __forceinline__ void mma_tf32(float* d, const uint32_t* a,
                                         uint32_t b0, uint32_t b1) {
    asm volatile(
        "mma.sync.aligned.m16n8k8.row.col.f32.tf32.tf32.f32 "
        "{%0,%1,%2,%3}, {%4,%5,%6,%7}, {%8,%9}, {%0,%1,%2,%3};"
        : "+f"(d[0]), "+f"(d[1]), "+f"(d[2]), "+f"(d[3])
        : "r"(a[0]), "r"(a[1]), "r"(a[2]), "r"(a[3]), "r"(b0), "r"(b1));
}

__global__ __launch_bounds__(NT, 1)
void attn_mma_kernel(const float* __restrict__ Q,
                     const float* __restrict__ K,
                     const float* __restrict__ V,
                     float* __restrict__ O,
                     int N)
{
    extern __shared__ float smem[];

    const int tid  = threadIdx.x;
    const int w    = tid >> 5;
    const int lane = tid & 31;
    const int qr   = lane >> 2;   // group id: row within mma tile
    const int qt   = lane & 3;    // thread-in-group: col-pair / k index
    const int wrow = w * 16;      // warp's first q-row in tile

    const int qtile = (int)gridDim.x - 1 - (int)blockIdx.x;  // long CTAs first
    const int h     = blockIdx.y;
    const int b     = blockIdx.z;
    const int qbase = qtile * BM;
    const size_t base = (size_t)b * N * DMODEL + (size_t)h * HEAD_DIM;

    // ---- preload Q fragments (tf32, scale folded), k pairing: slot t <-> d=2t, t+4 <-> 2t+1 ----
    uint32_t qa[8][4];
    {
        const float* q0 = Q + base + (size_t)(qbase + wrow + qr) * DMODEL;
        const float* q1 = q0 + 8 * DMODEL;
        #pragma unroll
        for (int ks = 0; ks < 8; ++ks) {
            const float2 v0 = *(const float2*)(q0 + ks * 8 + 2 * qt);
            const float2 v1 = *(const float2*)(q1 + ks * 8 + 2 * qt);
            qa[ks][0] = tf32_rna(v0.x * SC);   // a0: row m,   slot qt
            qa[ks][1] = tf32_rna(v1.x * SC);   // a1: row m+8, slot qt
            qa[ks][2] = tf32_rna(v0.y * SC);   // a2: row m,   slot qt+4
            qa[ks][3] = tf32_rna(v1.y * SC);   // a3: row m+8, slot qt+4
        }
    }

    // ---- prologue: fill K/V buffer 0 ----
    {
        const size_t kb = base;
        #pragma unroll
        for (int t = 0; t < 8; ++t) {
            const int idx = tid + t * NT;
            const int rr = idx >> 4, c4 = idx & 15;
            float4 kv = *(const float4*)(K + kb + (size_t)rr * DMODEL + c4 * 4);
            kv.x = __uint_as_float(tf32_rna(kv.x)); kv.y = __uint_as_float(tf32_rna(kv.y));
            kv.z = __uint_as_float(tf32_rna(kv.z)); kv.w = __uint_as_float(tf32_rna(kv.w));
            *(float4*)(smem + SK0 + rr * KS + c4 * 4) = kv;
            float4 vv = *(const float4*)(V + kb + (size_t)rr * DMODEL + c4 * 4);
            vv.x = __uint_as_float(tf32_rna(vv.x)); vv.y = __uint_as_float(tf32_rna(vv.y));
            vv.z = __uint_as_float(tf32_rna(vv.z)); vv.w = __uint_as_float(tf32_rna(vv.w));
            *(float4*)(smem + SV0 + rr * VS + c4 * 4) = vv;
        }
    }
    __syncthreads();

    float oAcc[8][4];
    #pragma unroll
    for (int dt = 0; dt < 8; ++dt) {
        #pragma unroll
        for (int e = 0; e < 4; ++e) oAcc[dt][e] = 0.0f;
    }
    float m0 = -1e30f, m1 = -1e30f, l0 = 0.0f, l1 = 0.0f;

    for (int kt = 0; kt <= qtile; ++kt) {
        const int cur = kt & 1;
        const float* sKc = smem + (cur ? SK1 : SK0);
        const float* sVc = smem + (cur ? SV1 : SV0);

        // ---- prefetch tile kt+1 into other buffer (overlaps with GEMM1 below) ----
        if (kt < qtile) {
            const size_t kb = base + (size_t)((kt + 1) * BN) * DMODEL;
            float* skd = smem + (cur ? SK0 : SK1);
            float* svd = smem + (cur ? SV0 : SV1);
            #pragma unroll
            for (int t = 0; t < 8; ++t) {
                const int idx = tid + t * NT;
                const int rr = idx >> 4, c4 = idx & 15;
                float4 kv = *(const float4*)(K + kb + (size_t)rr * DMODEL + c4 * 4);
                kv.x = __uint_as_float(tf32_rna(kv.x)); kv.y = __uint_as_float(tf32_rna(kv.y));
                kv.z = __uint_as_float(tf32_rna(kv.z)); kv.w = __uint_as_float(tf32_rna(kv.w));
                *(float4*)(skd + rr * KS + c4 * 4) = kv;
                float4 vv = *(const float4*)(V + kb + (size_t)rr * DMODEL + c4 * 4);
                vv.x = __uint_as_float(tf32_rna(vv.x)); vv.y = __uint_as_float(tf32_rna(vv.y));
                vv.z = __uint_as_float(tf32_rna(vv.z)); vv.w = __uint_as_float(tf32_rna(vv.w));
                *(float4*)(svd + rr * VS + c4 * 4) = vv;
            }
        }

        // ---- GEMM1: S = Qs K^T  (16 n-tiles x 8 k-slices) ----
        float s[16][4];
        #pragma unroll
        for (int nt = 0; nt < 16; ++nt) {
            #pragma unroll
            for (int e = 0; e < 4; ++e) s[nt][e] = 0.0f;
        }
        #pragma unroll
        for (int ks = 0; ks < 8; ++ks) {
            #pragma unroll
            for (int nt = 0; nt < 16; ++nt) {
                const uint2 bb = *(const uint2*)(sKc + (nt * 8 + qr) * KS + ks * 8 + 2 * qt);
                mma_tf32(s[nt], qa[ks], bb.x, bb.y);
            }
        }

        // ---- causal mask on diagonal tile ----
        if (kt == qtile) {
            const int r0 = wrow + qr, r1 = r0 + 8;
            #pragma unroll
            for (int nt = 0; nt < 16; ++nt) {
                const int c = nt * 8 + 2 * qt;
                if (c     > r0) s[nt][0] = -1e30f;
                if (c + 1 > r0) s[nt][1] = -1e30f;
                if (c     > r1) s[nt][2] = -1e30f;
                if (c + 1 > r1) s[nt][3] = -1e30f;
            }
        }

        // ---- warp-local online softmax (rows m, m+8) ----
        float mx0 = s[0][0], mx1 = s[0][2];
        #pragma unroll
        for (int nt = 0; nt < 16; ++nt) {
            mx0 = fmaxf(mx0, fmaxf(s[nt][0], s[nt][1]));
            mx1 = fmaxf(mx1, fmaxf(s[nt][2], s[nt][3]));
        }
        mx0 = fmaxf(mx0, __shfl_xor_sync(0xffffffffu, mx0, 1));
        mx0 = fmaxf(mx0, __shfl_xor_sync(0xffffffffu, mx0, 2));
        mx1 = fmaxf(mx1, __shfl_xor_sync(0xffffffffu, mx1, 1));
        mx1 = fmaxf(mx1, __shfl_xor_sync(0xffffffffu, mx1, 2));

        const float mn0 = fmaxf(m0, mx0);
        const float mn1 = fmaxf(m1, mx1);
        const float al0 = ex2f(m0 - mn0);
        const float al1 = ex2f(m1 - mn1);
        m0 = mn0; m1 = mn1;

        float rs0 = 0.0f, rs1 = 0.0f;
        #pragma unroll
        for (int nt = 0; nt < 16; ++nt) {
            s[nt][0] = ex2f(s[nt][0] - mn0);  rs0 += s[nt][0];
            s[nt][1] = ex2f(s[nt][1] - mn0);  rs0 += s[nt][1];
            s[nt][2] = ex2f(s[nt][2] - mn1);  rs1 += s[nt][2];
            s[nt][3] = ex2f(s[nt][3] - mn1);  rs1 += s[nt][3];
        }
        rs0 += __shfl_xor_sync(0xffffffffu, rs0, 1);
        rs0 += __shfl_xor_sync(0xffffffffu, rs0, 2);
        rs1 += __shfl_xor_sync(0xffffffffu, rs1, 1);
        rs1 += __shfl_xor_sync(0xffffffffu, rs1, 2);
        l0 = l0 * al0 + rs0;
        l1 = l1 * al1 + rs1;

        #pragma unroll
        for (int dt = 0; dt < 8; ++dt) {
            oAcc[dt][0] *= al0; oAcc[dt][1] *= al0;
            oAcc[dt][2] *= al1; oAcc[dt][3] *= al1;
        }

        // ---- GEMM2: O += P V  (P = S-frags reused as A: {c0,c2,c1,c3}) ----
        #pragma unroll
        for (int s8 = 0; s8 < 16; ++s8) {
            uint32_t pa[4];
            pa[0] = tf32_rna(s[s8][0]);   // row m,   n = 8*s8 + 2qt
            pa[1] = tf32_rna(s[s8][2]);   // row m+8, n = 8*s8 + 2qt
            pa[2] = tf32_rna(s[s8][1]);   // row m,   n = 8*s8 + 2qt+1
            pa[3] = tf32_rna(s[s8][3]);   // row m+8, n = 8*s8 + 2qt+1
            const float* vr0 = sVc + (s8 * 8 + 2 * qt) * VS + qr;
            const float* vr1 = vr0 + VS;
            #pragma unroll
            for (int dt = 0; dt < 8; ++dt) {
                const uint32_t b0 = __float_as_uint(vr0[dt * 8]);
                const uint32_t b1 = __float_as_uint(vr1[dt * 8]);
                mma_tf32(oAcc[dt], pa, b0, b1);
            }
        }

        __syncthreads();   // prefetch stores done; cur buffers free for next prefetch
    }

    // ---- epilogue: normalize and write ----
    const float il0 = 1.0f / l0;
    const float il1 = 1.0f / l1;
    float* o0 = O + base + (size_t)(qbase + wrow + qr) * DMODEL;
    float* o1 = o0 + 8 * DMODEL;
    #pragma unroll
    for (int dt = 0; dt < 8; ++dt) {
        *(float2*)(o0 + dt * 8 + 2 * qt) = make_float2(oAcc[dt][0] * il0, oAcc[dt][1] * il0);
        *(float2*)(o1 + dt * 8 + 2 * qt) = make_float2(oAcc[dt][2] * il1, oAcc[dt][3] * il1);
    }
}

extern "C" void kernel_launch(void* const* d_in, const int* in_sizes, int n_in,
                              void* d_out, int out_size)
{
    const float* q = (const float*)d_in[0];
    const float* k = (const float*)d_in[1];
    const float* v = (const float*)d_in[2];
    // d_in[3] is the causal mask (tril) — causality applied analytically.
    float* out = (float*)d_out;

    int N = 2048;
    if (n_in >= 4 && in_sizes[3] > 0) {
        double nn = sqrt((double)in_sizes[3]);
        N = (int)(nn + 0.5);
    }
    int B = in_sizes[0] / (N * DMODEL);

    static int smem_set = -1;
    if (smem_set != SMEM_BYTES) {
        cudaFuncSetAttribute(attn_mma_kernel,
                             cudaFuncAttributeMaxDynamicSharedMemorySize, SMEM_BYTES);
        smem_set = SMEM_BYTES;
    }

    dim3 grid(N / BM, NUM_HEADS, B);
    dim3 block(NT, 1, 1);
    attn_mma_kernel<<<grid, block, SMEM_BYTES>>>(q, k, v, out, N);
}